// round 8
// baseline (speedup 1.0000x reference)
#include <cuda_runtime.h>
#include <cstdint>

// Problem constants
#define BB 64
#define SS 512
#define HH 768
#define EE 128
#define TT_ 4
#define NT 5
#define H4 192            // H/4 float4 lanes
#define BLKS_PER_BATCH 16
#define ENH_PER_BLK 32    // 16*32 = 512 rows
#define EMB_PER_BLK 8     // 16*8  = 128 entities

// ---------------------------------------------------------------------------
// Single fused kernel. 1024 blocks = 64 batches x 16 blocks.
// Each block:
//   1) loads combined tables (type_table+conf_b, conf_w) into smem (18KB)
//   2) rebuilds its batch's per-token coefficient table in smem via packed
//      histogram atomics (counts: 5 x 6-bit fields in a uint; conf: float)
//   3) processes 32 enhance rows + 8 entity-embedding tasks (balanced mix).
// Emb tasks compute from hidden directly (enhanced = hidden + coef-combo),
// and their gathers hit L2 because sibling blocks stream the same batch.
// ---------------------------------------------------------------------------
__global__ void __launch_bounds__(H4, 8) fused_kernel(
    const float* __restrict__ hidden,       // [B,S,H]
    const int* __restrict__ types,          // [B,E]
    const float* __restrict__ conf,         // [B,E]
    const int* __restrict__ ent_tokens,     // [E,T]
    const float* __restrict__ type_table,   // [NT,H]
    const float* __restrict__ conf_w,       // [H]
    const float* __restrict__ conf_b,       // [H]
    float* __restrict__ out_enh,            // [B,S,H]
    float* __restrict__ out_emb) {          // [B,E,H]
    __shared__ float4 s_tab[NT + 1][H4];    // [0..4]=type_table+conf_b, [5]=conf_w
    __shared__ unsigned s_cnt[SS];          // packed type counts per token
    __shared__ float s_conf[SS];            // conf sum per token
    __shared__ int s_tok[EE * TT_];         // ent_tokens copy

    int tid = threadIdx.x;                  // 0..191
    int h = tid * 4;
    int b = blockIdx.x / BLKS_PER_BATCH;
    int j = blockIdx.x - b * BLKS_PER_BATCH;

    // tables
    {
        float4 cb4 = *reinterpret_cast<const float4*>(conf_b + h);
        s_tab[NT][tid] = *reinterpret_cast<const float4*>(conf_w + h);
#pragma unroll
        for (int ty = 0; ty < NT; ty++) {
            float4 v = *reinterpret_cast<const float4*>(type_table + ty * HH + h);
            s_tab[ty][tid] = make_float4(v.x + cb4.x, v.y + cb4.y, v.z + cb4.z, v.w + cb4.w);
        }
    }
    // zero histogram + stage tokens
    for (int i = tid; i < SS; i += H4) { s_cnt[i] = 0u; s_conf[i] = 0.f; }
    for (int i = tid; i < EE * TT_; i += H4) s_tok[i] = ent_tokens[i];
    __syncthreads();

    // per-batch histogram: 512 (e,t) pairs
    for (int p = tid; p < EE * TT_; p += H4) {
        int tok = s_tok[p];
        int e = p >> 2;
        int ty = __ldg(&types[b * EE + e]);
        float c = __ldg(&conf[b * EE + e]);
        atomicAdd(&s_cnt[tok], 1u << (6 * ty));
        atomicAdd(&s_conf[tok], c);
    }
    __syncthreads();

    const float* hb = hidden + (size_t)b * SS * HH;
    float* ob = out_enh + (size_t)b * SS * HH;

    // ---- 32 enhance rows ----
#pragma unroll 1
    for (int p = 0; p < ENH_PER_BLK; p++) {
        int s = j * ENH_PER_BLK + p;
        float4 v = *reinterpret_cast<const float4*>(hb + (size_t)s * HH + h);
        unsigned cnt = s_cnt[s];            // broadcast LDS
        if (cnt) {                          // uniform across block
#pragma unroll
            for (int q = 0; q < NT; q++) {
                unsigned a = (cnt >> (6 * q)) & 63u;
                if (a) {                    // uniform
                    float fa = (float)a;
                    float4 t = s_tab[q][tid];
                    v.x += fa * t.x; v.y += fa * t.y; v.z += fa * t.z; v.w += fa * t.w;
                }
            }
            float cs = s_conf[s];
            float4 t = s_tab[NT][tid];
            v.x += cs * t.x; v.y += cs * t.y; v.z += cs * t.z; v.w += cs * t.w;
        }
        *reinterpret_cast<float4*>(ob + (size_t)s * HH + h) = v;
    }

    // ---- 8 entity-embedding tasks ----
    float* eb = out_emb + (size_t)b * EE * HH;
#pragma unroll 1
    for (int q = 0; q < EMB_PER_BLK; q++) {
        int e = j * EMB_PER_BLK + q;
        float4 acc = make_float4(0.f, 0.f, 0.f, 0.f);
        float a0 = 0.f, a1 = 0.f, a2 = 0.f, a3 = 0.f, a4 = 0.f, ac = 0.f;
#pragma unroll
        for (int t = 0; t < TT_; t++) {
            int s = s_tok[e * TT_ + t];
            unsigned cnt = s_cnt[s];
            a0 += (float)(cnt & 63u);
            a1 += (float)((cnt >> 6) & 63u);
            a2 += (float)((cnt >> 12) & 63u);
            a3 += (float)((cnt >> 18) & 63u);
            a4 += (float)((cnt >> 24) & 63u);
            ac += s_conf[s];
            float4 v = *reinterpret_cast<const float4*>(hb + (size_t)s * HH + h);
            acc.x += v.x; acc.y += v.y; acc.z += v.z; acc.w += v.w;
        }
        float4 t;
        t = s_tab[0][tid]; acc.x += a0 * t.x; acc.y += a0 * t.y; acc.z += a0 * t.z; acc.w += a0 * t.w;
        t = s_tab[1][tid]; acc.x += a1 * t.x; acc.y += a1 * t.y; acc.z += a1 * t.z; acc.w += a1 * t.w;
        t = s_tab[2][tid]; acc.x += a2 * t.x; acc.y += a2 * t.y; acc.z += a2 * t.z; acc.w += a2 * t.w;
        t = s_tab[3][tid]; acc.x += a3 * t.x; acc.y += a3 * t.y; acc.z += a3 * t.z; acc.w += a3 * t.w;
        t = s_tab[4][tid]; acc.x += a4 * t.x; acc.y += a4 * t.y; acc.z += a4 * t.z; acc.w += a4 * t.w;
        t = s_tab[5][tid]; acc.x += ac * t.x; acc.y += ac * t.y; acc.z += ac * t.z; acc.w += ac * t.w;
        acc.x *= 0.25f; acc.y *= 0.25f; acc.z *= 0.25f; acc.w *= 0.25f;
        *reinterpret_cast<float4*>(eb + (size_t)e * HH + h) = acc;
    }
}

// ---------------------------------------------------------------------------
// Inputs in metadata order:
// 0 hidden_states (B,S,H) f32 | 1 entity_types (B,E) i32 | 2 entity_confidences (B,E) f32
// 3 ent_tokens (E,T) i32 | 4 type_table (NT,H) f32 | 5 conf_w (1,H) f32 | 6 conf_b (H) f32
// Output: enhanced (B,S,H) then entity_embeddings (B,E,H), concatenated.
// ---------------------------------------------------------------------------
extern "C" void kernel_launch(void* const* d_in, const int* in_sizes, int n_in,
                              void* d_out, int out_size) {
    const float* hidden   = (const float*)d_in[0];
    const int*   types    = (const int*)d_in[1];
    const float* conf     = (const float*)d_in[2];
    const int*   ent_tok  = (const int*)d_in[3];
    const float* ttab     = (const float*)d_in[4];
    const float* conf_w   = (const float*)d_in[5];
    const float* conf_b   = (const float*)d_in[6];

    float* out_enh = (float*)d_out;
    float* out_emb = out_enh + (size_t)BB * SS * HH;

    fused_kernel<<<BB * BLKS_PER_BATCH, H4>>>(
        hidden, types, conf, ent_tok, ttab, conf_w, conf_b, out_enh, out_emb);
}

// round 9
// speedup vs baseline: 1.4417x; 1.4417x over previous
#include <cuda_runtime.h>
#include <cstdint>

// Problem constants
#define BB 64
#define SS 512
#define HH 768
#define EE 128
#define TT_ 4
#define NT 5
#define H4 192   // H/4 float4 lanes

// Scratch (no allocs allowed). Packed per-(b,s) coefficients:
//   .x = 5 x 6-bit type counts, .y = float conf-sum (as bits)
__device__ uint2 g_coef[BB * SS];

// ---------------------------------------------------------------------------
// P: per-batch coefficient build. One block per batch b (512 threads, one per
// flat (e,t)). Packed histogram in smem, 8-byte store per row.
// ---------------------------------------------------------------------------
__global__ void __launch_bounds__(512) rowcoef_kernel(
    const int* __restrict__ ent_tokens,     // [E,T]
    const int* __restrict__ types,          // [B,E]
    const float* __restrict__ conf) {       // [B,E]
    __shared__ unsigned s_cnt[SS];
    __shared__ float s_conf[SS];
    int b = blockIdx.x;
    int tid = threadIdx.x;                  // 0..511 == flat (e,t)

    s_cnt[tid] = 0u;
    s_conf[tid] = 0.f;
    __syncthreads();

    int tok = ent_tokens[tid];
    int e = tid >> 2;
    int ty = types[b * EE + e];
    float c = conf[b * EE + e];
    atomicAdd(&s_cnt[tok], 1u << (6 * ty));
    atomicAdd(&s_conf[tok], c);
    __syncthreads();

    g_coef[b * SS + tid] = make_uint2(s_cnt[tid], __float_as_uint(s_conf[tid]));
}

// ---------------------------------------------------------------------------
// Fused main kernel: R6 structure (persistent grid-stride, smem tables,
// uniform-sparsity combine) with coefficients packed to 8 bytes:
// one LDG.64 per enhance row instead of two LDG.128 (L1 wavefronts -18%,
// coef table L2-resident at 256KB).
// ---------------------------------------------------------------------------
__global__ void __launch_bounds__(H4, 8) fused_kernel(
    const float* __restrict__ hidden,       // [B,S,H]
    const int* __restrict__ ent_tokens,     // [E,T]
    const float* __restrict__ type_table,   // [NT,H]
    const float* __restrict__ conf_w,       // [H]
    const float* __restrict__ conf_b,       // [H]
    float* __restrict__ out_enh,            // [B,S,H]
    float* __restrict__ out_emb) {          // [B,E,H]
    __shared__ float4 s_tab[NT + 1][H4];    // [0..4]=type_table+conf_b, [5]=conf_w
    int tid = threadIdx.x;                  // 0..191
    int h = tid * 4;

    {
        float4 cb4 = *reinterpret_cast<const float4*>(conf_b + h);
        s_tab[NT][tid] = *reinterpret_cast<const float4*>(conf_w + h);
#pragma unroll
        for (int ty = 0; ty < NT; ty++) {
            float4 v = *reinterpret_cast<const float4*>(type_table + ty * HH + h);
            s_tab[ty][tid] = make_float4(v.x + cb4.x, v.y + cb4.y, v.z + cb4.z, v.w + cb4.w);
        }
    }
    __syncthreads();

    const int NTASK = BB * (SS + EE);
    for (int idx = blockIdx.x; idx < NTASK; idx += gridDim.x) {
        int b = idx / (SS + EE);
        int r = idx - b * (SS + EE);
        const float* hb = hidden + (size_t)b * SS * HH;

        if (r < SS) {
            // ---- enhance row (b, s=r) ----
            int s = r;
            uint2 cc = __ldg(&g_coef[b * SS + s]);
            float4 v = *reinterpret_cast<const float4*>(hb + (size_t)s * HH + h);
            unsigned cnt = cc.x;
            if (cnt) {                       // uniform: row has entities
#pragma unroll
                for (int q = 0; q < NT; q++) {
                    unsigned a = (cnt >> (6 * q)) & 63u;
                    if (a) {                 // uniform
                        float fa = (float)a;
                        float4 t = s_tab[q][tid];
                        v.x += fa * t.x; v.y += fa * t.y;
                        v.z += fa * t.z; v.w += fa * t.w;
                    }
                }
                float cs = __uint_as_float(cc.y);
                float4 t = s_tab[NT][tid];
                v.x += cs * t.x; v.y += cs * t.y; v.z += cs * t.z; v.w += cs * t.w;
            }
            *reinterpret_cast<float4*>(out_enh + ((size_t)b * SS + s) * HH + h) = v;
        } else {
            // ---- entity embedding (b, e): 0.25 * sum_t enhanced[b, tok, :] ----
            int e = r - SS;
            float4 acc = make_float4(0.f, 0.f, 0.f, 0.f);
            float a0 = 0.f, a1 = 0.f, a2 = 0.f, a3 = 0.f, a4 = 0.f, ac = 0.f;
#pragma unroll
            for (int t = 0; t < TT_; t++) {
                int s = __ldg(&ent_tokens[e * TT_ + t]);
                uint2 cc = __ldg(&g_coef[b * SS + s]);
                unsigned cnt = cc.x;
                a0 += (float)(cnt & 63u);
                a1 += (float)((cnt >> 6) & 63u);
                a2 += (float)((cnt >> 12) & 63u);
                a3 += (float)((cnt >> 18) & 63u);
                a4 += (float)((cnt >> 24) & 63u);
                ac += __uint_as_float(cc.y);
                float4 v = *reinterpret_cast<const float4*>(hb + (size_t)s * HH + h);
                acc.x += v.x; acc.y += v.y; acc.z += v.z; acc.w += v.w;
            }
            float4 t;
            t = s_tab[0][tid]; acc.x += a0 * t.x; acc.y += a0 * t.y; acc.z += a0 * t.z; acc.w += a0 * t.w;
            t = s_tab[1][tid]; acc.x += a1 * t.x; acc.y += a1 * t.y; acc.z += a1 * t.z; acc.w += a1 * t.w;
            t = s_tab[2][tid]; acc.x += a2 * t.x; acc.y += a2 * t.y; acc.z += a2 * t.z; acc.w += a2 * t.w;
            t = s_tab[3][tid]; acc.x += a3 * t.x; acc.y += a3 * t.y; acc.z += a3 * t.z; acc.w += a3 * t.w;
            t = s_tab[4][tid]; acc.x += a4 * t.x; acc.y += a4 * t.y; acc.z += a4 * t.z; acc.w += a4 * t.w;
            t = s_tab[5][tid]; acc.x += ac * t.x; acc.y += ac * t.y; acc.z += ac * t.z; acc.w += ac * t.w;
            acc.x *= 0.25f; acc.y *= 0.25f; acc.z *= 0.25f; acc.w *= 0.25f;
            *reinterpret_cast<float4*>(out_emb + ((size_t)b * EE + e) * HH + h) = acc;
        }
    }
}

// ---------------------------------------------------------------------------
// Inputs in metadata order:
// 0 hidden_states (B,S,H) f32 | 1 entity_types (B,E) i32 | 2 entity_confidences (B,E) f32
// 3 ent_tokens (E,T) i32 | 4 type_table (NT,H) f32 | 5 conf_w (1,H) f32 | 6 conf_b (H) f32
// Output: enhanced (B,S,H) then entity_embeddings (B,E,H), concatenated.
// ---------------------------------------------------------------------------
extern "C" void kernel_launch(void* const* d_in, const int* in_sizes, int n_in,
                              void* d_out, int out_size) {
    const float* hidden   = (const float*)d_in[0];
    const int*   types    = (const int*)d_in[1];
    const float* conf     = (const float*)d_in[2];
    const int*   ent_tok  = (const int*)d_in[3];
    const float* ttab     = (const float*)d_in[4];
    const float* conf_w   = (const float*)d_in[5];
    const float* conf_b   = (const float*)d_in[6];

    float* out_enh = (float*)d_out;
    float* out_emb = out_enh + (size_t)BB * SS * HH;

    rowcoef_kernel<<<BB, 512>>>(ent_tok, types, conf);
    fused_kernel<<<1184, H4>>>(hidden, ent_tok, ttab, conf_w, conf_b,
                               out_enh, out_emb);
}